// round 1
// baseline (speedup 1.0000x reference)
#include <cuda_runtime.h>
#include <cuda_bf16.h>
#include <mma.h>
#include <math.h>

using namespace nvcuda;

// Problem constants
#define TOK   4096          // B*S
#define DMODEL 1024
#define NEXP  8
#define HDIM  4096
#define NASSIGN (TOK*2)     // top_k = 2

// GEMM tiling
#define BM 128
#define BN 64
#define BK 32
#define GTHREADS 128
#define A_STRIDE 36         // BK + 4 pad (16B multiple)
#define B_STRIDE 68         // BN + 4 pad
#define C_STRIDE 68
#define A_BUF (BM*A_STRIDE)     // 4608 floats
#define B_BUF (BK*B_STRIDE)     // 2176 floats
#define SMEM_FLOATS (2*A_BUF + 2*B_BUF)   // 13568
#define SMEM_BYTES (SMEM_FLOATS*4)        // 54272

// Scratch (device globals: allocation-free rule)
__device__ int   g_expert_off[NEXP+1];
__device__ int   g_perm_tok[NASSIGN];
__device__ float g_perm_gate[NASSIGN];
__device__ int   g_tok_exp[NASSIGN];
__device__ float g_tok_gate[NASSIGN];
__device__ float g_hbuf[(size_t)NASSIGN * HDIM];   // 8192 x 4096 fp32 = 134 MB

__device__ __forceinline__ float gelu_tanh(float v) {
    const float c = 0.7978845608028654f;
    float u = c * (v + 0.044715f * v * v * v);
    return 0.5f * v * (1.0f + tanhf(u));
}

// ---------------------------------------------------------------------------
// Router: one warp per token. Computes logits & noise-logits (E=8 each),
// noisy = logits + noise*softplus(noise_logits), gate1 = softmax(noisy),
// top-2 indices + renormalized top-2 softmax gates.
// ---------------------------------------------------------------------------
__global__ void __launch_bounds__(256) router_kernel(
    const float* __restrict__ x, const float* __restrict__ noise,
    const float* __restrict__ wr, const float* __restrict__ br,
    const float* __restrict__ wn, const float* __restrict__ bn,
    float* __restrict__ gate1)
{
    int warp = (blockIdx.x * blockDim.x + threadIdx.x) >> 5;
    int lane = threadIdx.x & 31;
    if (warp >= TOK) return;

    const float* xr = x + (size_t)warp * DMODEL;
    float ar[8] = {0,0,0,0,0,0,0,0};
    float an[8] = {0,0,0,0,0,0,0,0};

    #pragma unroll 8
    for (int j = 0; j < DMODEL/32; j++) {
        int d = j*32 + lane;
        float xv = xr[d];
        const float4* w4r = reinterpret_cast<const float4*>(wr + (size_t)d*8);
        const float4* w4n = reinterpret_cast<const float4*>(wn + (size_t)d*8);
        float4 r0 = w4r[0], r1 = w4r[1];
        float4 n0 = w4n[0], n1 = w4n[1];
        ar[0] = fmaf(xv, r0.x, ar[0]); ar[1] = fmaf(xv, r0.y, ar[1]);
        ar[2] = fmaf(xv, r0.z, ar[2]); ar[3] = fmaf(xv, r0.w, ar[3]);
        ar[4] = fmaf(xv, r1.x, ar[4]); ar[5] = fmaf(xv, r1.y, ar[5]);
        ar[6] = fmaf(xv, r1.z, ar[6]); ar[7] = fmaf(xv, r1.w, ar[7]);
        an[0] = fmaf(xv, n0.x, an[0]); an[1] = fmaf(xv, n0.y, an[1]);
        an[2] = fmaf(xv, n0.z, an[2]); an[3] = fmaf(xv, n0.w, an[3]);
        an[4] = fmaf(xv, n1.x, an[4]); an[5] = fmaf(xv, n1.y, an[5]);
        an[6] = fmaf(xv, n1.z, an[6]); an[7] = fmaf(xv, n1.w, an[7]);
    }
    #pragma unroll
    for (int e = 0; e < 8; e++) {
        #pragma unroll
        for (int o = 16; o > 0; o >>= 1) {
            ar[e] += __shfl_xor_sync(0xffffffffu, ar[e], o);
            an[e] += __shfl_xor_sync(0xffffffffu, an[e], o);
        }
    }
    if (lane == 0) {
        float nv[8];
        float mx = -1e30f;
        #pragma unroll
        for (int e = 0; e < 8; e++) {
            float l  = ar[e] + br[e];
            float nl = an[e] + bn[e];
            // softplus = max(x,0) + log1p(exp(-|x|))
            float sp = fmaxf(nl, 0.0f) + log1pf(expf(-fabsf(nl)));
            float v = l + noise[(size_t)warp*8 + e] * sp;
            nv[e] = v;
            mx = fmaxf(mx, v);
        }
        float s = 0.0f;
        #pragma unroll
        for (int e = 0; e < 8; e++) s += expf(nv[e] - mx);
        float inv = 1.0f / s;
        #pragma unroll
        for (int e = 0; e < 8; e++) gate1[(size_t)warp*8 + e] = expf(nv[e] - mx) * inv;
        // top-2 (first occurrence on ties, matching lax.top_k)
        int i0 = 0;
        #pragma unroll
        for (int e = 1; e < 8; e++) if (nv[e] > nv[i0]) i0 = e;
        int i1 = -1;
        #pragma unroll
        for (int e = 0; e < 8; e++) {
            if (e == i0) continue;
            if (i1 < 0 || nv[e] > nv[i1]) i1 = e;
        }
        float ex = expf(nv[i1] - nv[i0]);   // <= 1
        float den = 1.0f + ex;
        g_tok_exp[warp*2 + 0]  = i0;
        g_tok_exp[warp*2 + 1]  = i1;
        g_tok_gate[warp*2 + 0] = 1.0f / den;
        g_tok_gate[warp*2 + 1] = ex / den;
    }
}

// ---------------------------------------------------------------------------
// Deterministic stable partition of 8192 assignments into per-expert lists.
// Single block, 256 threads, counting sort with exact prefix scans.
// ---------------------------------------------------------------------------
__global__ void __launch_bounds__(256) partition_kernel()
{
    __shared__ int cnt[256][8];
    __shared__ int tot[8];
    __shared__ int base[9];
    int tid = threadIdx.x;
    int a0 = tid * 32;               // 32 assignments per thread (16 tokens)

    int local[8] = {0,0,0,0,0,0,0,0};
    for (int i = 0; i < 32; i++) local[g_tok_exp[a0 + i]]++;
    #pragma unroll
    for (int e = 0; e < 8; e++) cnt[tid][e] = local[e];
    __syncthreads();

    if (tid < 8) {
        int run = 0;
        for (int i = 0; i < 256; i++) { int v = cnt[i][tid]; cnt[i][tid] = run; run += v; }
        tot[tid] = run;
    }
    __syncthreads();
    if (tid == 0) {
        int acc = 0;
        for (int e = 0; e < 8; e++) { base[e] = acc; acc += tot[e]; }
        base[8] = acc;
        for (int e = 0; e <= 8; e++) g_expert_off[e] = base[e];
    }
    __syncthreads();

    int run2[8];
    #pragma unroll
    for (int e = 0; e < 8; e++) run2[e] = base[e] + cnt[tid][e];
    for (int i = 0; i < 32; i++) {
        int a = a0 + i;
        int e = g_tok_exp[a];
        int p = run2[e]++;
        g_perm_tok[p]  = a >> 1;          // token id
        g_perm_gate[p] = g_tok_gate[a];
    }
}

// ---------------------------------------------------------------------------
// GEMM1: h = gelu( gather(x) @ w_fc[e] + b_fc[e] ),  K=1024, N=4096
// tf32 WMMA, 128x64 tile, BK=32, double-buffered smem.
// ---------------------------------------------------------------------------
__global__ void __launch_bounds__(GTHREADS) fc_gelu_kernel(
    const float* __restrict__ x, const float* __restrict__ wfc,
    const float* __restrict__ bfc)
{
    extern __shared__ float smem[];
    int by = blockIdx.y;
    int e = by >> 5, m = by & 31;
    int off = g_expert_off[e];
    int cnt = g_expert_off[e+1] - off;
    if (m * BM >= cnt) return;
    int mbase = off + m * BM;
    int rv = min(cnt - m * BM, BM);
    int n0 = blockIdx.x * BN;
    int tid = threadIdx.x;
    int wid = tid >> 5;
    int wm = wid & 1, wn = wid >> 1;

    const float* wptr = wfc + (size_t)e * DMODEL * HDIM;

    // A row pointers (gathered tokens)
    const float* aPtr[8];
    #pragma unroll
    for (int t = 0; t < 8; t++) {
        int idx = tid + t*GTHREADS;
        int row = idx >> 3, seg = idx & 7;
        int r = min(row, rv - 1);
        aPtr[t] = x + (size_t)g_perm_tok[mbase + r] * DMODEL + seg*4;
    }
    const float* bPtr[4];
    #pragma unroll
    for (int t = 0; t < 4; t++) {
        int idx = tid + t*GTHREADS;
        int k = idx >> 4, seg = idx & 15;
        bPtr[t] = wptr + (size_t)k * HDIM + n0 + seg*4;
    }

    wmma::fragment<wmma::matrix_a, 16,16,8, wmma::precision::tf32, wmma::row_major> fa[4];
    wmma::fragment<wmma::matrix_b, 16,16,8, wmma::precision::tf32, wmma::row_major> fb[2];
    wmma::fragment<wmma::accumulator, 16,16,8, float> fc[4][2];
    #pragma unroll
    for (int i = 0; i < 4; i++)
        #pragma unroll
        for (int j = 0; j < 2; j++) wmma::fill_fragment(fc[i][j], 0.0f);

    float4 rA[8], rB[4];
    #pragma unroll
    for (int t = 0; t < 8; t++) rA[t] = *reinterpret_cast<const float4*>(aPtr[t]);
    #pragma unroll
    for (int t = 0; t < 4; t++) rB[t] = *reinterpret_cast<const float4*>(bPtr[t]);

    // store stage 0 (converted to tf32)
    {
        float* As = smem;
        float* Bs = smem + 2*A_BUF;
        #pragma unroll
        for (int t = 0; t < 8; t++) {
            int idx = tid + t*GTHREADS;
            int row = idx >> 3, seg = idx & 7;
            float4 v;
            v.x = wmma::__float_to_tf32(rA[t].x); v.y = wmma::__float_to_tf32(rA[t].y);
            v.z = wmma::__float_to_tf32(rA[t].z); v.w = wmma::__float_to_tf32(rA[t].w);
            *reinterpret_cast<float4*>(As + row*A_STRIDE + seg*4) = v;
        }
        #pragma unroll
        for (int t = 0; t < 4; t++) {
            int idx = tid + t*GTHREADS;
            int k = idx >> 4, seg = idx & 15;
            float4 v;
            v.x = wmma::__float_to_tf32(rB[t].x); v.y = wmma::__float_to_tf32(rB[t].y);
            v.z = wmma::__float_to_tf32(rB[t].z); v.w = wmma::__float_to_tf32(rB[t].w);
            *reinterpret_cast<float4*>(Bs + k*B_STRIDE + seg*4) = v;
        }
    }
    __syncthreads();

    const int nK = DMODEL / BK;   // 32
    for (int kt = 0; kt < nK; kt++) {
        int cur = kt & 1;
        bool more = (kt + 1 < nK);
        if (more) {
            #pragma unroll
            for (int t = 0; t < 8; t++)
                rA[t] = *reinterpret_cast<const float4*>(aPtr[t] + (size_t)(kt+1)*BK);
            #pragma unroll
            for (int t = 0; t < 4; t++)
                rB[t] = *reinterpret_cast<const float4*>(bPtr[t] + (size_t)(kt+1)*BK*HDIM);
        }
        float* Ac = smem + cur*A_BUF;
        float* Bc = smem + 2*A_BUF + cur*B_BUF;
        #pragma unroll
        for (int ks = 0; ks < 4; ks++) {
            int kk = ks*8;
            #pragma unroll
            for (int i = 0; i < 4; i++)
                wmma::load_matrix_sync(fa[i], Ac + (wm*64 + i*16)*A_STRIDE + kk, A_STRIDE);
            #pragma unroll
            for (int j = 0; j < 2; j++)
                wmma::load_matrix_sync(fb[j], Bc + kk*B_STRIDE + wn*32 + j*16, B_STRIDE);
            #pragma unroll
            for (int i = 0; i < 4; i++)
                #pragma unroll
                for (int j = 0; j < 2; j++)
                    wmma::mma_sync(fc[i][j], fa[i], fb[j], fc[i][j]);
        }
        if (more) {
            int nb = cur ^ 1;
            float* As = smem + nb*A_BUF;
            float* Bs = smem + 2*A_BUF + nb*B_BUF;
            #pragma unroll
            for (int t = 0; t < 8; t++) {
                int idx = tid + t*GTHREADS;
                int row = idx >> 3, seg = idx & 7;
                float4 v;
                v.x = wmma::__float_to_tf32(rA[t].x); v.y = wmma::__float_to_tf32(rA[t].y);
                v.z = wmma::__float_to_tf32(rA[t].z); v.w = wmma::__float_to_tf32(rA[t].w);
                *reinterpret_cast<float4*>(As + row*A_STRIDE + seg*4) = v;
            }
            #pragma unroll
            for (int t = 0; t < 4; t++) {
                int idx = tid + t*GTHREADS;
                int k = idx >> 4, seg = idx & 15;
                float4 v;
                v.x = wmma::__float_to_tf32(rB[t].x); v.y = wmma::__float_to_tf32(rB[t].y);
                v.z = wmma::__float_to_tf32(rB[t].z); v.w = wmma::__float_to_tf32(rB[t].w);
                *reinterpret_cast<float4*>(Bs + k*B_STRIDE + seg*4) = v;
            }
        }
        __syncthreads();
    }

    // epilogue: C -> smem -> bias + gelu -> hbuf
    float* Cs = smem;
    #pragma unroll
    for (int i = 0; i < 4; i++)
        #pragma unroll
        for (int j = 0; j < 2; j++)
            wmma::store_matrix_sync(Cs + (wm*64 + i*16)*C_STRIDE + wn*32 + j*16,
                                    fc[i][j], C_STRIDE, wmma::mem_row_major);
    __syncthreads();

    #pragma unroll
    for (int t = 0; t < 16; t++) {
        int idx = tid + t*GTHREADS;     // 0..2047
        int row = idx >> 4, seg = idx & 15;
        if (row < rv) {
            float4 v = *reinterpret_cast<const float4*>(Cs + row*C_STRIDE + seg*4);
            float4 bb = *reinterpret_cast<const float4*>(bfc + (size_t)e*HDIM + n0 + seg*4);
            float4 o;
            o.x = gelu_tanh(v.x + bb.x);
            o.y = gelu_tanh(v.y + bb.y);
            o.z = gelu_tanh(v.z + bb.z);
            o.w = gelu_tanh(v.w + bb.w);
            *reinterpret_cast<float4*>(g_hbuf + (size_t)(mbase + row)*HDIM + n0 + seg*4) = o;
        }
    }
}

// ---------------------------------------------------------------------------
// GEMM2: y = h @ w_proj[e] + b_proj[e];  out[token] += gate * y  (atomicAdd)
// K=4096, N=1024.
// ---------------------------------------------------------------------------
__global__ void __launch_bounds__(GTHREADS) proj_scatter_kernel(
    const float* __restrict__ wproj, const float* __restrict__ bproj,
    float* __restrict__ out)
{
    extern __shared__ float smem[];
    int by = blockIdx.y;
    int e = by >> 5, m = by & 31;
    int off = g_expert_off[e];
    int cnt = g_expert_off[e+1] - off;
    if (m * BM >= cnt) return;
    int mbase = off + m * BM;
    int rv = min(cnt - m * BM, BM);
    int n0 = blockIdx.x * BN;
    int tid = threadIdx.x;
    int wid = tid >> 5;
    int wm = wid & 1, wn = wid >> 1;

    const float* wptr = wproj + (size_t)e * HDIM * DMODEL;

    const float* aPtr[8];
    #pragma unroll
    for (int t = 0; t < 8; t++) {
        int idx = tid + t*GTHREADS;
        int row = idx >> 3, seg = idx & 7;
        int r = min(row, rv - 1);
        aPtr[t] = g_hbuf + (size_t)(mbase + r) * HDIM + seg*4;
    }
    const float* bPtr[4];
    #pragma unroll
    for (int t = 0; t < 4; t++) {
        int idx = tid + t*GTHREADS;
        int k = idx >> 4, seg = idx & 15;
        bPtr[t] = wptr + (size_t)k * DMODEL + n0 + seg*4;
    }

    wmma::fragment<wmma::matrix_a, 16,16,8, wmma::precision::tf32, wmma::row_major> fa[4];
    wmma::fragment<wmma::matrix_b, 16,16,8, wmma::precision::tf32, wmma::row_major> fb[2];
    wmma::fragment<wmma::accumulator, 16,16,8, float> fc[4][2];
    #pragma unroll
    for (int i = 0; i < 4; i++)
        #pragma unroll
        for (int j = 0; j < 2; j++) wmma::fill_fragment(fc[i][j], 0.0f);

    float4 rA[8], rB[4];
    #pragma unroll
    for (int t = 0; t < 8; t++) rA[t] = *reinterpret_cast<const float4*>(aPtr[t]);
    #pragma unroll
    for (int t = 0; t < 4; t++) rB[t] = *reinterpret_cast<const float4*>(bPtr[t]);
    {
        float* As = smem;
        float* Bs = smem + 2*A_BUF;
        #pragma unroll
        for (int t = 0; t < 8; t++) {
            int idx = tid + t*GTHREADS;
            int row = idx >> 3, seg = idx & 7;
            float4 v;
            v.x = wmma::__float_to_tf32(rA[t].x); v.y = wmma::__float_to_tf32(rA[t].y);
            v.z = wmma::__float_to_tf32(rA[t].z); v.w = wmma::__float_to_tf32(rA[t].w);
            *reinterpret_cast<float4*>(As + row*A_STRIDE + seg*4) = v;
        }
        #pragma unroll
        for (int t = 0; t < 4; t++) {
            int idx = tid + t*GTHREADS;
            int k = idx >> 4, seg = idx & 15;
            float4 v;
            v.x = wmma::__float_to_tf32(rB[t].x); v.y = wmma::__float_to_tf32(rB[t].y);
            v.z = wmma::__float_to_tf32(rB[t].z); v.w = wmma::__float_to_tf32(rB[t].w);
            *reinterpret_cast<float4*>(Bs + k*B_STRIDE + seg*4) = v;
        }
    }
    __syncthreads();

    const int nK = HDIM / BK;   // 128
    for (int kt = 0; kt < nK; kt++) {
        int cur = kt & 1;
        bool more = (kt + 1 < nK);
        if (more) {
            #pragma unroll
            for (int t = 0; t < 8; t++)
                rA[t] = *reinterpret_cast<const float4*>(aPtr[t] + (size_t)(kt+1)*BK);
            #pragma unroll
            for (int t = 0; t < 4; t++)
                rB[t] = *reinterpret_cast<const float4*>(bPtr[t] + (size_t)(kt+1)*BK*DMODEL);
        }
        float* Ac = smem + cur*A_BUF;
        float* Bc = smem + 2*A_BUF + cur*B_BUF;
        #pragma unroll
        for (int ks = 0; ks < 4; ks++) {
            int kk = ks*8;
            #pragma unroll
            for (int i = 0; i < 4; i++)
                wmma::load_matrix_sync(fa[i], Ac + (wm*64 + i*16)*A_STRIDE + kk, A_STRIDE);
            #pragma unroll
            for (int j = 0; j < 2; j++)
                wmma::load_matrix_sync(fb[j], Bc + kk*B_STRIDE + wn*32 + j*16, B_STRIDE);
            #pragma unroll
            for (int i = 0; i < 4; i++)
                #pragma unroll
                for (int j = 0; j < 2; j++)
                    wmma::mma_sync(fc[i][j], fa[i], fb[j], fc[i][j]);
        }
        if (more) {
            int nb = cur ^ 1;
            float* As = smem + nb*A_BUF;
            float* Bs = smem + 2*A_BUF + nb*B_BUF;
            #pragma unroll
            for (int t = 0; t < 8; t++) {
                int idx = tid + t*GTHREADS;
                int row = idx >> 3, seg = idx & 7;
                float4 v;
                v.x = wmma::__float_to_tf32(rA[t].x); v.y = wmma::__float_to_tf32(rA[t].y);
                v.z = wmma::__float_to_tf32(rA[t].z); v.w = wmma::__float_to_tf32(rA[t].w);
                *reinterpret_cast<float4*>(As + row*A_STRIDE + seg*4) = v;
            }
            #pragma unroll
            for (int t = 0; t < 4; t++) {
                int idx = tid + t*GTHREADS;
                int k = idx >> 4, seg = idx & 15;
                float4 v;
                v.x = wmma::__float_to_tf32(rB[t].x); v.y = wmma::__float_to_tf32(rB[t].y);
                v.z = wmma::__float_to_tf32(rB[t].z); v.w = wmma::__float_to_tf32(rB[t].w);
                *reinterpret_cast<float4*>(Bs + k*B_STRIDE + seg*4) = v;
            }
        }
        __syncthreads();
    }

    float* Cs = smem;
    #pragma unroll
    for (int i = 0; i < 4; i++)
        #pragma unroll
        for (int j = 0; j < 2; j++)
            wmma::store_matrix_sync(Cs + (wm*64 + i*16)*C_STRIDE + wn*32 + j*16,
                                    fc[i][j], C_STRIDE, wmma::mem_row_major);
    __syncthreads();

    #pragma unroll
    for (int t = 0; t < 16; t++) {
        int idx = tid + t*GTHREADS;
        int row = idx >> 4, seg = idx & 15;
        if (row < rv) {
            int r = mbase + row;
            float g = g_perm_gate[r];
            int tok = g_perm_tok[r];
            float4 v = *reinterpret_cast<const float4*>(Cs + row*C_STRIDE + seg*4);
            float4 bb = *reinterpret_cast<const float4*>(bproj + (size_t)e*DMODEL + n0 + seg*4);
            float* op = out + (size_t)tok*DMODEL + n0 + seg*4;
            atomicAdd(op + 0, (v.x + bb.x) * g);
            atomicAdd(op + 1, (v.y + bb.y) * g);
            atomicAdd(op + 2, (v.z + bb.z) * g);
            atomicAdd(op + 3, (v.w + bb.w) * g);
        }
    }
}

// ---------------------------------------------------------------------------
extern "C" void kernel_launch(void* const* d_in, const int* in_sizes, int n_in,
                              void* d_out, int out_size)
{
    const float* x      = (const float*)d_in[0];
    const float* noise  = (const float*)d_in[1];
    const float* wroute = (const float*)d_in[2];
    const float* broute = (const float*)d_in[3];
    const float* wnoise = (const float*)d_in[4];
    const float* bnoise = (const float*)d_in[5];
    const float* wfc    = (const float*)d_in[6];
    const float* bfc    = (const float*)d_in[7];
    const float* wproj  = (const float*)d_in[8];
    const float* bproj  = (const float*)d_in[9];

    float* out   = (float*)d_out;
    float* gate1 = out + (size_t)TOK * DMODEL;

    cudaFuncSetAttribute(fc_gelu_kernel,
        cudaFuncAttributeMaxDynamicSharedMemorySize, SMEM_BYTES);
    cudaFuncSetAttribute(proj_scatter_kernel,
        cudaFuncAttributeMaxDynamicSharedMemorySize, SMEM_BYTES);

    cudaMemsetAsync(out, 0, (size_t)TOK * DMODEL * sizeof(float));

    router_kernel<<<TOK/8, 256>>>(x, noise, wroute, broute, wnoise, bnoise, gate1);
    partition_kernel<<<1, 256>>>();

    dim3 g1(HDIM / BN, NEXP * 32);
    fc_gelu_kernel<<<g1, GTHREADS, SMEM_BYTES>>>(x, wfc, bfc);

    dim3 g2(DMODEL / BN, NEXP * 32);
    proj_scatter_kernel<<<g2, GTHREADS, SMEM_BYTES>>>(wproj, bproj, out);
}

// round 3
// speedup vs baseline: 2.0946x; 2.0946x over previous
#include <cuda_runtime.h>
#include <math.h>
#include <cstdint>

// Problem constants
#define TOK    4096
#define DMODEL 1024
#define NEXP   8
#define HDIM   4096
#define NASSIGN (TOK*2)

// GEMM tiling
#define BM 128
#define BN 128
#define BK 32
#define NSTAGE 3
#define LDA 36            // floats, padded (bank = 4g+tig, conflict-free)
#define LDB 136           // floats, padded (bank = 8tig+g, conflict-free)
#define A_BYTES (BM*LDA*4)            // 18432
#define B_BYTES (BK*LDB*4)            // 17408
#define STAGE_BYTES (A_BYTES + B_BYTES)   // 35840
#define SMEM_TOTAL (NSTAGE*STAGE_BYTES)   // 107520

// Scratch (device globals; allocation-free rule)
__device__ int   g_expert_off[NEXP+1];
__device__ int   g_perm_tok[NASSIGN];
__device__ int   g_inv_pos[NASSIGN];
__device__ int   g_tok_exp[NASSIGN];
__device__ float g_tok_gate[NASSIGN];
__device__ float g_hbuf[(size_t)NASSIGN * HDIM];    // fp32 activations
__device__ float g_ybuf[(size_t)NASSIGN * DMODEL];  // fp32 per-assignment y

// ---------------------------------------------------------------------------
// helpers
// ---------------------------------------------------------------------------
__device__ __forceinline__ uint32_t smem_u32(const void* p) {
    uint32_t a;
    asm("{ .reg .u64 t; cvta.to.shared.u64 t, %1; cvt.u32.u64 %0, t; }" : "=r"(a) : "l"(p));
    return a;
}
__device__ __forceinline__ uint32_t cvt_tf32(float x) {
    uint32_t r; asm("cvt.rna.tf32.f32 %0, %1;" : "=r"(r) : "f"(x)); return r;
}
#define CP_ASYNC16(dst, src) \
    asm volatile("cp.async.cg.shared.global [%0], [%1], 16;" :: "r"(dst), "l"(src))
#define CP_COMMIT() asm volatile("cp.async.commit_group;")
#define CP_WAIT1()  asm volatile("cp.async.wait_group 1;")

__device__ __forceinline__ void mma_tf32(float* c, const uint32_t* a, const uint32_t* b) {
    asm volatile(
        "mma.sync.aligned.m16n8k8.row.col.f32.tf32.tf32.f32 "
        "{%0,%1,%2,%3}, {%4,%5,%6,%7}, {%8,%9}, {%0,%1,%2,%3};"
        : "+f"(c[0]), "+f"(c[1]), "+f"(c[2]), "+f"(c[3])
        : "r"(a[0]), "r"(a[1]), "r"(a[2]), "r"(a[3]), "r"(b[0]), "r"(b[1]));
}

__device__ __forceinline__ float gelu_tanh(float v) {
    const float c = 0.7978845608028654f;
    float u = c * (v + 0.044715f * v * v * v);
    return 0.5f * v * (1.0f + tanhf(u));
}

// ---------------------------------------------------------------------------
// Router: one warp per token
// ---------------------------------------------------------------------------
__global__ void __launch_bounds__(256) router_kernel(
    const float* __restrict__ x, const float* __restrict__ noise,
    const float* __restrict__ wr, const float* __restrict__ br,
    const float* __restrict__ wn, const float* __restrict__ bn,
    float* __restrict__ gate1)
{
    int warp = (blockIdx.x * blockDim.x + threadIdx.x) >> 5;
    int lane = threadIdx.x & 31;
    if (warp >= TOK) return;

    const float* xr = x + (size_t)warp * DMODEL;
    float ar[8] = {0,0,0,0,0,0,0,0};
    float an[8] = {0,0,0,0,0,0,0,0};

    #pragma unroll 8
    for (int j = 0; j < DMODEL/32; j++) {
        int d = j*32 + lane;
        float xv = xr[d];
        const float4* w4r = reinterpret_cast<const float4*>(wr + (size_t)d*8);
        const float4* w4n = reinterpret_cast<const float4*>(wn + (size_t)d*8);
        float4 r0 = w4r[0], r1 = w4r[1];
        float4 n0 = w4n[0], n1 = w4n[1];
        ar[0] = fmaf(xv, r0.x, ar[0]); ar[1] = fmaf(xv, r0.y, ar[1]);
        ar[2] = fmaf(xv, r0.z, ar[2]); ar[3] = fmaf(xv, r0.w, ar[3]);
        ar[4] = fmaf(xv, r1.x, ar[4]); ar[5] = fmaf(xv, r1.y, ar[5]);
        ar[6] = fmaf(xv, r1.z, ar[6]); ar[7] = fmaf(xv, r1.w, ar[7]);
        an[0] = fmaf(xv, n0.x, an[0]); an[1] = fmaf(xv, n0.y, an[1]);
        an[2] = fmaf(xv, n0.z, an[2]); an[3] = fmaf(xv, n0.w, an[3]);
        an[4] = fmaf(xv, n1.x, an[4]); an[5] = fmaf(xv, n1.y, an[5]);
        an[6] = fmaf(xv, n1.z, an[6]); an[7] = fmaf(xv, n1.w, an[7]);
    }
    #pragma unroll
    for (int e = 0; e < 8; e++) {
        #pragma unroll
        for (int o = 16; o > 0; o >>= 1) {
            ar[e] += __shfl_xor_sync(0xffffffffu, ar[e], o);
            an[e] += __shfl_xor_sync(0xffffffffu, an[e], o);
        }
    }
    if (lane == 0) {
        float nv[8];
        float mx = -1e30f;
        #pragma unroll
        for (int e = 0; e < 8; e++) {
            float l  = ar[e] + br[e];
            float nl = an[e] + bn[e];
            float sp = fmaxf(nl, 0.0f) + log1pf(expf(-fabsf(nl)));
            float v = l + noise[(size_t)warp*8 + e] * sp;
            nv[e] = v;
            mx = fmaxf(mx, v);
        }
        float s = 0.0f;
        #pragma unroll
        for (int e = 0; e < 8; e++) s += expf(nv[e] - mx);
        float inv = 1.0f / s;
        #pragma unroll
        for (int e = 0; e < 8; e++) gate1[(size_t)warp*8 + e] = expf(nv[e] - mx) * inv;
        int i0 = 0;
        #pragma unroll
        for (int e = 1; e < 8; e++) if (nv[e] > nv[i0]) i0 = e;
        int i1 = -1;
        #pragma unroll
        for (int e = 0; e < 8; e++) {
            if (e == i0) continue;
            if (i1 < 0 || nv[e] > nv[i1]) i1 = e;
        }
        float ex = expf(nv[i1] - nv[i0]);
        float den = 1.0f + ex;
        g_tok_exp[warp*2 + 0]  = i0;
        g_tok_exp[warp*2 + 1]  = i1;
        g_tok_gate[warp*2 + 0] = 1.0f / den;
        g_tok_gate[warp*2 + 1] = ex / den;
    }
}

// ---------------------------------------------------------------------------
// Deterministic stable partition + inverse permutation
// ---------------------------------------------------------------------------
__global__ void __launch_bounds__(256) partition_kernel()
{
    __shared__ int cnt[256][8];
    __shared__ int tot[8];
    __shared__ int base[9];
    int tid = threadIdx.x;
    int a0 = tid * 32;

    int local[8] = {0,0,0,0,0,0,0,0};
    for (int i = 0; i < 32; i++) local[g_tok_exp[a0 + i]]++;
    #pragma unroll
    for (int e = 0; e < 8; e++) cnt[tid][e] = local[e];
    __syncthreads();

    if (tid < 8) {
        int run = 0;
        for (int i = 0; i < 256; i++) { int v = cnt[i][tid]; cnt[i][tid] = run; run += v; }
        tot[tid] = run;
    }
    __syncthreads();
    if (tid == 0) {
        int acc = 0;
        for (int e = 0; e < 8; e++) { base[e] = acc; acc += tot[e]; }
        base[8] = acc;
        for (int e = 0; e <= 8; e++) g_expert_off[e] = base[e];
    }
    __syncthreads();

    int run2[8];
    #pragma unroll
    for (int e = 0; e < 8; e++) run2[e] = base[e] + cnt[tid][e];
    for (int i = 0; i < 32; i++) {
        int a = a0 + i;
        int e = g_tok_exp[a];
        int p = run2[e]++;
        g_perm_tok[p] = a >> 1;
        g_inv_pos[a]  = p;
    }
}

// ---------------------------------------------------------------------------
// tf32 mma.sync GEMM, 128x128 tile, BK=32, cp.async 3-stage pipeline.
// IS_FC: A = gathered x rows (K=1024), Out = gelu(D + b_fc) -> g_hbuf (N=4096)
// else:  A = g_hbuf rows (K=4096),     Out = D + b_proj     -> g_ybuf (N=1024)
// ---------------------------------------------------------------------------
template<int K, int NTOT, bool IS_FC>
__global__ void __launch_bounds__(256) moe_gemm_kernel(
    const float* __restrict__ Ain,
    const float* __restrict__ W,
    const float* __restrict__ bias)
{
    constexpr int NCH = K / BK;
    extern __shared__ char smem[];

    int e = blockIdx.y >> 6, m = blockIdx.y & 63;
    int off = g_expert_off[e];
    int cnt = g_expert_off[e+1] - off;
    if (m * BM >= cnt) return;
    int mbase = off + m * BM;
    int rv = min(cnt - m * BM, BM);
    int n0 = blockIdx.x * BN;

    int tid = threadIdx.x;
    int wid = tid >> 5, lane = tid & 31;
    int wm = wid & 1, wn = wid >> 1;          // 2 x 4 warp grid
    int g = lane >> 2, tig = lane & 3;

    uint32_t sbase = smem_u32(smem);
    const float* A = IS_FC ? Ain : g_hbuf;
    const float* wbase = W + (size_t)e * K * NTOT + n0;

    // cp.async source pointers / smem dst offsets (4 A-chunks + 4 B-chunks per thread)
    const char* aSrc[4]; uint32_t aDst[4];
    const char* bSrc[4]; uint32_t bDst[4];
    #pragma unroll
    for (int i = 0; i < 4; i++) {
        int c = i*256 + tid;
        int row = c >> 3, q = c & 7;                  // 128 rows x 8 x 16B
        int r = min(row, rv - 1);
        int arow = IS_FC ? g_perm_tok[mbase + r] : (mbase + r);
        aSrc[i] = (const char*)(A + (size_t)arow * K) + q*16;
        aDst[i] = row * (LDA*4) + q*16;
    }
    #pragma unroll
    for (int i = 0; i < 4; i++) {
        int c = i*256 + tid;
        int row = c >> 5, c16 = c & 31;               // 32 rows x 32 x 16B
        bSrc[i] = (const char*)(wbase + (size_t)row * NTOT) + c16*16;
        bDst[i] = row * (LDB*4) + c16*16;
    }

    float acc[4][4][4];
    #pragma unroll
    for (int i = 0; i < 4; i++)
        #pragma unroll
        for (int j = 0; j < 4; j++)
            #pragma unroll
            for (int v = 0; v < 4; v++) acc[i][j][v] = 0.0f;

    // ---- pipeline ----
    auto issue = [&](int kt) {
        uint32_t base = sbase + (uint32_t)(kt % NSTAGE) * STAGE_BYTES;
        #pragma unroll
        for (int i = 0; i < 4; i++)
            CP_ASYNC16(base + aDst[i], aSrc[i] + (size_t)kt * (BK*4));
        #pragma unroll
        for (int i = 0; i < 4; i++)
            CP_ASYNC16(base + A_BYTES + bDst[i], bSrc[i] + (size_t)kt * ((size_t)BK * NTOT * 4));
    };

    issue(0); CP_COMMIT();
    issue(1); CP_COMMIT();

    for (int kt = 0; kt < NCH; kt++) {
        CP_WAIT1();
        __syncthreads();
        if (kt + 2 < NCH) issue(kt + 2);
        CP_COMMIT();

        const float* As = (const float*)(smem + (kt % NSTAGE) * STAGE_BYTES);
        const float* Bs = (const float*)(smem + (kt % NSTAGE) * STAGE_BYTES + A_BYTES);

        #pragma unroll
        for (int ks = 0; ks < 4; ks++) {
            uint32_t af[4][4], bf[4][2];
            #pragma unroll
            for (int mf = 0; mf < 4; mf++) {
                const float* p = As + (wm*64 + mf*16 + g) * LDA + ks*8 + tig;
                af[mf][0] = cvt_tf32(p[0]);
                af[mf][2] = cvt_tf32(p[4]);
                af[mf][1] = cvt_tf32(p[8*LDA]);
                af[mf][3] = cvt_tf32(p[8*LDA + 4]);
            }
            #pragma unroll
            for (int nf = 0; nf < 4; nf++) {
                const float* p = Bs + (ks*8 + tig) * LDB + wn*32 + nf*8 + g;
                bf[nf][0] = cvt_tf32(p[0]);
                bf[nf][1] = cvt_tf32(p[4*LDB]);
            }
            #pragma unroll
            for (int mf = 0; mf < 4; mf++)
                #pragma unroll
                for (int nf = 0; nf < 4; nf++)
                    mma_tf32(acc[mf][nf], af[mf], bf[nf]);
        }
    }

    // ---- epilogue: bias (+gelu), direct global stores ----
    float* Out = IS_FC ? g_hbuf : g_ybuf;
    const float* brow = bias + (size_t)e * NTOT + n0;

    #pragma unroll
    for (int mf = 0; mf < 4; mf++) {
        int r0 = wm*64 + mf*16 + g;
        int r1 = r0 + 8;
        float* o0 = Out + (size_t)(mbase + r0) * NTOT + n0;
        float* o1 = Out + (size_t)(mbase + r1) * NTOT + n0;
        #pragma unroll
        for (int nf = 0; nf < 4; nf++) {
            int col = wn*32 + nf*8 + tig*2;
            float2 bb = *reinterpret_cast<const float2*>(brow + col);
            if (r0 < rv) {
                float v0 = acc[mf][nf][0] + bb.x;
                float v1 = acc[mf][nf][1] + bb.y;
                float2 o;
                if (IS_FC) { o.x = gelu_tanh(v0); o.y = gelu_tanh(v1); }
                else       { o.x = v0;            o.y = v1; }
                *reinterpret_cast<float2*>(o0 + col) = o;
            }
            if (r1 < rv) {
                float v2 = acc[mf][nf][2] + bb.x;
                float v3 = acc[mf][nf][3] + bb.y;
                float2 o;
                if (IS_FC) { o.x = gelu_tanh(v2); o.y = gelu_tanh(v3); }
                else       { o.x = v2;            o.y = v3; }
                *reinterpret_cast<float2*>(o1 + col) = o;
            }
        }
    }
}

// ---------------------------------------------------------------------------
// Combine: out[t] = g0 * y[p0] + g1 * y[p1]   (deterministic, no atomics)
// ---------------------------------------------------------------------------
__global__ void __launch_bounds__(256) combine_kernel(float* __restrict__ out)
{
    int t = blockIdx.x;
    int j = threadIdx.x;
    int p0 = g_inv_pos[2*t], p1 = g_inv_pos[2*t+1];
    float g0 = g_tok_gate[2*t], g1 = g_tok_gate[2*t+1];
    const float4* y0 = reinterpret_cast<const float4*>(g_ybuf + (size_t)p0 * DMODEL);
    const float4* y1 = reinterpret_cast<const float4*>(g_ybuf + (size_t)p1 * DMODEL);
    float4 a = y0[j], b = y1[j];
    float4 o;
    o.x = g0*a.x + g1*b.x; o.y = g0*a.y + g1*b.y;
    o.z = g0*a.z + g1*b.z; o.w = g0*a.w + g1*b.w;
    reinterpret_cast<float4*>(out + (size_t)t * DMODEL)[j] = o;
}

// ---------------------------------------------------------------------------
extern "C" void kernel_launch(void* const* d_in, const int* in_sizes, int n_in,
                              void* d_out, int out_size)
{
    const float* x      = (const float*)d_in[0];
    const float* noise  = (const float*)d_in[1];
    const float* wroute = (const float*)d_in[2];
    const float* broute = (const float*)d_in[3];
    const float* wnoise = (const float*)d_in[4];
    const float* bnoise = (const float*)d_in[5];
    const float* wfc    = (const float*)d_in[6];
    const float* bfc    = (const float*)d_in[7];
    const float* wproj  = (const float*)d_in[8];
    const float* bproj  = (const float*)d_in[9];

    float* out   = (float*)d_out;
    float* gate1 = out + (size_t)TOK * DMODEL;

    cudaFuncSetAttribute((const void*)moe_gemm_kernel<DMODEL, HDIM, true>,
        cudaFuncAttributeMaxDynamicSharedMemorySize, SMEM_TOTAL);
    cudaFuncSetAttribute((const void*)moe_gemm_kernel<HDIM, DMODEL, false>,
        cudaFuncAttributeMaxDynamicSharedMemorySize, SMEM_TOTAL);

    router_kernel<<<TOK/8, 256>>>(x, noise, wroute, broute, wnoise, bnoise, gate1);
    partition_kernel<<<1, 256>>>();

    dim3 g1(HDIM / BN, NEXP * 64);     // 32 x 512
    moe_gemm_kernel<DMODEL, HDIM, true><<<g1, 256, SMEM_TOTAL>>>(x, wfc, bfc);

    dim3 g2(DMODEL / BN, NEXP * 64);   // 8 x 512
    moe_gemm_kernel<HDIM, DMODEL, false><<<g2, 256, SMEM_TOTAL>>>(x, wproj, bproj);

    combine_kernel<<<TOK, 256>>>(out);
}